// round 3
// baseline (speedup 1.0000x reference)
#include <cuda_runtime.h>
#include <cstdint>

#define S_LEN 128
#define BB 32
#define VOC 32000
#define NHID 1024
#define NHEADS 16
#define HD 64
#define NCTA 128
#define TPB 256

// ---------------- device scratch (no allocations allowed) ----------------
__device__ float g_keys[(S_LEN + 1) * BB * NHID];
__device__ float g_vals[(S_LEN + 1) * BB * NHID];
__device__ float g_emb[S_LEN * BB * NHID];
__device__ float g_xi[BB * 4 * NHID];     // [b][ e(virtual) | q | attn | hidden ]
__device__ float g_inter[BB * 4 * NHID];
__device__ float g_part[16 * BB * 4096];  // split-K partials
__device__ unsigned g_bar;                // monotonic grid-barrier counter

// ---------------- grid barrier (monotonic; replay-safe) ----------------
__device__ __forceinline__ void gbar() {
    __threadfence();
    __syncthreads();
    if (threadIdx.x == 0) {
        unsigned a = atomicAdd(&g_bar, 1u) + 1u;
        unsigned target = ((a + NCTA - 1u) / NCTA) * NCTA;
        while (*(volatile unsigned*)&g_bar < target) { __nanosleep(64); }
        __threadfence();
    }
    __syncthreads();
}

// ---------------- block reduce (sum, sumsq) ----------------
__device__ float2 blk_reduce2(float a, float b, float* s_red) {
#pragma unroll
    for (int o = 16; o > 0; o >>= 1) {
        a += __shfl_xor_sync(0xffffffffu, a, o);
        b += __shfl_xor_sync(0xffffffffu, b, o);
    }
    int w = threadIdx.x >> 5, l = threadIdx.x & 31;
    if (l == 0) { s_red[w] = a; s_red[8 + w] = b; }
    __syncthreads();
    if (threadIdx.x == 0) {
        float sa = 0.f, sb = 0.f;
#pragma unroll
        for (int i = 0; i < 8; i++) { sa += s_red[i]; sb += s_red[8 + i]; }
        s_red[16] = sa; s_red[17] = sb;
    }
    __syncthreads();
    return make_float2(s_red[16], s_red[17]);
}

// ---------------- split-K small-M GEMM phase ----------------
// PHASE 0: q   out[32][1024], K=2048, x=[emb|hidden]
// PHASE 1: int out[32][4096], K=4096, x=[emb|q|attn|hidden]
// PHASE 2: fin out[32][3072], K=4096, x=inter
template <int PHASE>
__device__ void gemm_phase(int step, const float* __restrict__ W, float* s_mem) {
    constexpr int N   = (PHASE == 0) ? 1024 : ((PHASE == 1) ? 4096 : 3072);
    constexpr int K   = (PHASE == 0) ? 2048 : 4096;
    constexpr int NT  = (PHASE == 0) ? 128 : 256;
    constexpr int TN  = NT / 64;
    constexpr int NTILES = N / NT;
    constexpr int KSPL   = (PHASE == 0) ? 16 : 8;
    constexpr int KCH    = K / KSPL;

    int cta = blockIdx.x;
    if (cta >= NTILES * KSPL) return;
    int nt = cta % NTILES, ks = cta / NTILES;
    int tid = threadIdx.x;
    int b0 = (tid >> 6) * 8;
    int n0 = nt * NT + (tid & 63) * TN;
    const float* emb = g_emb + (size_t)step * (BB * NHID);

    float acc[8][TN];
#pragma unroll
    for (int i = 0; i < 8; i++)
#pragma unroll
        for (int j = 0; j < TN; j++) acc[i][j] = 0.f;

    const int kbase0 = ks * KCH;
    for (int kt = 0; kt < KCH; kt += 64) {
        int kb = kbase0 + kt;
        // stage x[32][64] transposed into s_mem[k*36 + b]
#pragma unroll
        for (int r = 0; r < 8; r++) {
            int idx = tid + r * TPB;
            int bbx = idx >> 6, kk = idx & 63;
            int k = kb + kk;
            float v;
            if (PHASE == 0)
                v = (k < 1024) ? __ldg(&emb[bbx * 1024 + k]) : __ldcg(&g_xi[bbx * 4096 + 2048 + k]);
            else if (PHASE == 1)
                v = (k < 1024) ? __ldg(&emb[bbx * 1024 + k]) : __ldcg(&g_xi[bbx * 4096 + k]);
            else
                v = __ldcg(&g_inter[bbx * 4096 + k]);
            s_mem[kk * 36 + bbx] = v;
        }
        __syncthreads();
#pragma unroll
        for (int kk = 0; kk < 64; kk += 4) {
            float4 wv[TN];
#pragma unroll
            for (int j = 0; j < TN; j++)
                wv[j] = __ldg((const float4*)(W + (size_t)(n0 + j) * K + kb + kk));
#pragma unroll
            for (int c = 0; c < 4; c++) {
                float4 xa = *(const float4*)&s_mem[(kk + c) * 36 + b0];
                float4 xb = *(const float4*)&s_mem[(kk + c) * 36 + b0 + 4];
                float xs[8] = {xa.x, xa.y, xa.z, xa.w, xb.x, xb.y, xb.z, xb.w};
#pragma unroll
                for (int i = 0; i < 8; i++)
#pragma unroll
                    for (int j = 0; j < TN; j++)
                        acc[i][j] += xs[i] * (&wv[j].x)[c];
            }
        }
        __syncthreads();
    }
#pragma unroll
    for (int i = 0; i < 8; i++)
#pragma unroll
        for (int j = 0; j < TN; j++)
            g_part[(size_t)(ks * BB + b0 + i) * N + n0 + j] = acc[i][j];
}

// ---------------- fused split-K reduce + bias + LayerNorm + ReLU ----------------
template <int PHASE>
__device__ void ln_phase(int step, const float* __restrict__ bias,
                         const float* __restrict__ gam, const float* __restrict__ bet,
                         float* __restrict__ states_out, float* s_mem) {
    constexpr int N = (PHASE == 0) ? 1024 : ((PHASE == 1) ? 4096 : 3072);
    constexpr int KSPL = (PHASE == 0) ? 16 : 8;
    int b = blockIdx.x;
    if (b >= BB) return;
    int tid = threadIdx.x;
    float* s_red = s_mem + 4096;

    float lsum = 0.f, lsq = 0.f;
    for (int n = tid; n < N; n += TPB) {
        float v = __ldg(&bias[n]);
#pragma unroll
        for (int ks = 0; ks < KSPL; ks++)
            v += __ldcg(&g_part[(size_t)(ks * BB + b) * N + n]);
        s_mem[n] = v;
        lsum += v; lsq += v * v;
    }
    float2 r = blk_reduce2(lsum, lsq, s_red);
    float mu = r.x / (float)N;
    float var = r.y / (float)N - mu * mu;
    float rstd = rsqrtf(var + 1e-5f);

    for (int n = tid; n < N; n += TPB) {
        float v = (s_mem[n] - mu) * rstd * __ldg(&gam[n]) + __ldg(&bet[n]);
        v = fmaxf(v, 0.f);
        if (PHASE == 0) {
            g_xi[b * 4096 + 1024 + n] = v;
        } else if (PHASE == 1) {
            g_inter[b * 4096 + n] = v;
        } else {
            if (n < 1024)
                g_keys[((size_t)(step + 1) * BB + b) * NHID + n] = v;
            else if (n < 2048)
                g_vals[((size_t)(step + 1) * BB + b) * NHID + (n - 1024)] = v;
            else {
                g_xi[b * 4096 + 3072 + (n - 2048)] = v;
                states_out[((size_t)(step + 1) * BB + b) * NHID + (n - 2048)] = v;
            }
        }
    }
}

// ---------------- attention: one warp per (b, head) pair ----------------
__device__ void attn_phase(int step, float* s_mem) {
    int wid = (blockIdx.x << 3) + (threadIdx.x >> 5);
    int lane = threadIdx.x & 31;
    if (wid >= BB * NHEADS) return;
    int b = wid >> 4, n = wid & 15;

    const float* qp = &g_xi[b * 4096 + 1024 + n * 64];
    float4 qv[16];
#pragma unroll
    for (int t = 0; t < 16; t++) qv[t] = __ldcg((const float4*)(qp + t * 4));

    int cnt = step + 1;  // valid cache entries c = 0..step
    float sc[5];
#pragma unroll
    for (int t = 0; t < 5; t++) sc[t] = -1e30f;
    for (int t = 0; t < 5; t++) {
        int c = lane + t * 32;
        if (c < cnt) {
            const float* kp = &g_keys[((size_t)c * BB + b) * NHID + n * 64];
            float d = 0.f;
#pragma unroll
            for (int u = 0; u < 16; u++) {
                float4 kv = __ldcg((const float4*)(kp + u * 4));
                d += qv[u].x * kv.x + qv[u].y * kv.y + qv[u].z * kv.z + qv[u].w * kv.w;
            }
            sc[t] = d * 0.125f;
        }
    }
    float m = sc[0];
#pragma unroll
    for (int t = 1; t < 5; t++) m = fmaxf(m, sc[t]);
#pragma unroll
    for (int o = 16; o > 0; o >>= 1) m = fmaxf(m, __shfl_xor_sync(0xffffffffu, m, o));
    float p[5]; float lsum = 0.f;
    for (int t = 0; t < 5; t++) {
        int c = lane + t * 32;
        p[t] = (c < cnt) ? __expf(sc[t] - m) : 0.f;
        lsum += p[t];
    }
#pragma unroll
    for (int o = 16; o > 0; o >>= 1) lsum += __shfl_xor_sync(0xffffffffu, lsum, o);
    float inv = 1.f / lsum;
    float* sw = s_mem + (threadIdx.x >> 5) * 132;
    for (int t = 0; t < 5; t++) {
        int c = lane + t * 32;
        if (c < cnt) sw[c] = p[t] * inv;
    }
    __syncwarp();

    float a0 = 0.f, a1 = 0.f;
    for (int c = 0; c < cnt; c++) {
        float w = sw[c];
        const float* vp = &g_vals[((size_t)c * BB + b) * NHID + n * 64];
        a0 += w * __ldcg(vp + lane);
        a1 += w * __ldcg(vp + lane + 32);
    }
    g_xi[b * 4096 + 2048 + n * 64 + lane] = a0;
    g_xi[b * 4096 + 2048 + n * 64 + lane + 32] = a1;
}

// ---------------- persistent recurrence kernel ----------------
__global__ void __launch_bounds__(TPB, 1) rnn_kernel(
    const float* __restrict__ q_w, const float* __restrict__ q_b,
    const float* __restrict__ qn_g, const float* __restrict__ qn_b,
    const float* __restrict__ int_w, const float* __restrict__ int_b,
    const float* __restrict__ intn_g, const float* __restrict__ intn_b,
    const float* __restrict__ fin_w, const float* __restrict__ fin_b,
    const float* __restrict__ fn_g, const float* __restrict__ fn_b,
    float* __restrict__ states_out) {
    __shared__ __align__(16) float s_mem[4160];
    for (int step = 0; step < S_LEN; step++) {
        gemm_phase<0>(step, q_w, s_mem);                                  gbar();
        ln_phase<0>(step, q_b, qn_g, qn_b, nullptr, s_mem);               gbar();
        attn_phase(step, s_mem);                                          gbar();
        gemm_phase<1>(step, int_w, s_mem);                                gbar();
        ln_phase<1>(step, int_b, intn_g, intn_b, nullptr, s_mem);         gbar();
        gemm_phase<2>(step, fin_w, s_mem);                                gbar();
        ln_phase<2>(step, fin_b, fn_g, fn_b, states_out, s_mem);          gbar();
    }
}

// ---------------- embedding gather ----------------
__global__ void embed_kernel(const int* __restrict__ obs, const float* __restrict__ enc_w) {
    int r = blockIdx.x;  // r = s*32 + b
    int tok = __ldg(&obs[r]);
    const float4* src = (const float4*)(enc_w + (size_t)tok * NHID);
    float4* dst = (float4*)(g_emb + (size_t)r * NHID);
    dst[threadIdx.x] = __ldg(&src[threadIdx.x]);
}

// ---------------- init: caches, hidden, states_full[0] ----------------
__global__ void init_kernel(const float* __restrict__ h0, const float* __restrict__ kc,
                            const float* __restrict__ vc, float* __restrict__ states_out) {
    int b = blockIdx.x;  // 0..31
    int t = threadIdx.x; // 0..255, one float4 each
    const float4* k4 = (const float4*)(kc + (size_t)b * NHID);
    const float4* v4 = (const float4*)(vc + (size_t)b * NHID);
    const float4* h4 = (const float4*)(h0 + (size_t)b * NHID);
    ((float4*)(g_keys + (size_t)b * NHID))[t] = k4[t];
    ((float4*)(g_vals + (size_t)b * NHID))[t] = v4[t];
    float4 hv = h4[t];
    ((float4*)(g_xi + (size_t)b * 4096 + 3072))[t] = hv;
    ((float4*)(states_out + (size_t)b * NHID))[t] = hv;
}

// ---------------- decoder GEMM: [4096 x 32000] = states[4096 x 1024] @ dec_w^T ----------------
#define DBM 128
#define DBN 64
#define DBK 16
__global__ void __launch_bounds__(256) dec_kernel(const float* __restrict__ A,
                                                  const float* __restrict__ Wd,
                                                  const float* __restrict__ bias,
                                                  float* __restrict__ out) {
    __shared__ __align__(16) float As[DBK][DBM + 4];
    __shared__ __align__(16) float Bs[DBK][DBN + 4];
    int tid = threadIdx.x;
    int mb = blockIdx.y * DBM, nb = blockIdx.x * DBN;
    int tx = tid & 15, ty = tid >> 4;

    float acc[8][4];
#pragma unroll
    for (int i = 0; i < 8; i++)
#pragma unroll
        for (int j = 0; j < 4; j++) acc[i][j] = 0.f;

    for (int kb = 0; kb < NHID; kb += DBK) {
#pragma unroll
        for (int r = 0; r < 8; r++) {
            int idx = tid + r * 256;
            int m = idx >> 4, k = idx & 15;
            As[k][m] = __ldg(&A[(size_t)(mb + m) * NHID + kb + k]);
        }
        {
            int n = tid >> 2, kq = (tid & 3) * 4;
            float4 v = __ldg((const float4*)&Wd[(size_t)(nb + n) * NHID + kb + kq]);
            Bs[kq][n] = v.x; Bs[kq + 1][n] = v.y; Bs[kq + 2][n] = v.z; Bs[kq + 3][n] = v.w;
        }
        __syncthreads();
#pragma unroll
        for (int k = 0; k < DBK; k++) {
            float4 a0 = *(const float4*)&As[k][ty * 8];
            float4 a1 = *(const float4*)&As[k][ty * 8 + 4];
            float4 bv = *(const float4*)&Bs[k][tx * 4];
            float av[8] = {a0.x, a0.y, a0.z, a0.w, a1.x, a1.y, a1.z, a1.w};
            float bb[4] = {bv.x, bv.y, bv.z, bv.w};
#pragma unroll
            for (int i = 0; i < 8; i++)
#pragma unroll
                for (int j = 0; j < 4; j++) acc[i][j] += av[i] * bb[j];
        }
        __syncthreads();
    }
#pragma unroll
    for (int i = 0; i < 8; i++) {
        int m = mb + ty * 8 + i;
#pragma unroll
        for (int j = 0; j < 4; j++) {
            int n = nb + tx * 4 + j;
            out[(size_t)m * VOC + n] = acc[i][j] + __ldg(&bias[n]);
        }
    }
}

extern "C" void kernel_launch(void* const* d_in, const int* in_sizes, int n_in,
                              void* d_out, int out_size) {
    const int*   obs    = (const int*)d_in[0];
    const float* h0     = (const float*)d_in[1];
    const float* kc     = (const float*)d_in[2];
    const float* vc     = (const float*)d_in[3];
    const float* enc_w  = (const float*)d_in[4];
    const float* q_w    = (const float*)d_in[5];
    const float* q_b    = (const float*)d_in[6];
    const float* qn_g   = (const float*)d_in[7];
    const float* qn_b   = (const float*)d_in[8];
    const float* int_w  = (const float*)d_in[9];
    const float* int_b  = (const float*)d_in[10];
    const float* intn_g = (const float*)d_in[11];
    const float* intn_b = (const float*)d_in[12];
    const float* fin_w  = (const float*)d_in[13];
    const float* fin_b  = (const float*)d_in[14];
    const float* fn_g   = (const float*)d_in[15];
    const float* fn_b   = (const float*)d_in[16];
    const float* dec_w  = (const float*)d_in[17];
    const float* dec_b  = (const float*)d_in[18];

    float* out = (float*)d_out;
    float* states_full = out + (size_t)S_LEN * BB * VOC;  // [S+1][B][NHID]

    init_kernel<<<BB, 256>>>(h0, kc, vc, states_full);
    embed_kernel<<<S_LEN * BB, 256>>>(obs, enc_w);
    rnn_kernel<<<NCTA, TPB>>>(q_w, q_b, qn_g, qn_b, int_w, int_b, intn_g, intn_b,
                              fin_w, fin_b, fn_g, fn_b, states_full);
    dec_kernel<<<dim3(VOC / DBN, (S_LEN * BB) / DBM), 256>>>(
        states_full + (size_t)BB * NHID, dec_w, dec_b, out);
}

// round 5
// speedup vs baseline: 1.1599x; 1.1599x over previous
#include <cuda_runtime.h>
#include <cuda_bf16.h>
#include <cstdint>

#define S_LEN 128
#define BB 32
#define VOC 32000
#define NHID 1024
#define NHEADS 16
#define HD 64
#define NCTA 128
#define TPB 256

// ---------------- device scratch (no allocations allowed) ----------------
__device__ float g_keys[(S_LEN + 1) * BB * NHID];
__device__ float g_vals[(S_LEN + 1) * BB * NHID];
__device__ float g_emb[S_LEN * BB * NHID];
__device__ float g_xi[BB * 4 * NHID];     // [b][ e(virtual) | q | attn | hidden ]
__device__ float g_inter[BB * 4 * NHID];
__device__ float g_part[16 * BB * 4096];  // split-K partials
__device__ unsigned g_bar;                // monotonic grid-barrier counter

// bf16x3 split operands for the decoder GEMM
__device__ __nv_bfloat16 g_whi[(size_t)VOC * NHID];
__device__ __nv_bfloat16 g_wlo[(size_t)VOC * NHID];
__device__ __nv_bfloat16 g_ahi[(size_t)S_LEN * BB * NHID];
__device__ __nv_bfloat16 g_alo[(size_t)S_LEN * BB * NHID];

// ---------------- grid barrier (monotonic; replay-safe) ----------------
__device__ __forceinline__ void gbar() {
    __threadfence();
    __syncthreads();
    if (threadIdx.x == 0) {
        unsigned a = atomicAdd(&g_bar, 1u) + 1u;
        unsigned target = ((a + NCTA - 1u) / NCTA) * NCTA;
        while (*(volatile unsigned*)&g_bar < target) { __nanosleep(64); }
        __threadfence();
    }
    __syncthreads();
}

// ---------------- block reduce (sum, sumsq) ----------------
__device__ float2 blk_reduce2(float a, float b, float* s_red) {
#pragma unroll
    for (int o = 16; o > 0; o >>= 1) {
        a += __shfl_xor_sync(0xffffffffu, a, o);
        b += __shfl_xor_sync(0xffffffffu, b, o);
    }
    int w = threadIdx.x >> 5, l = threadIdx.x & 31;
    if (l == 0) { s_red[w] = a; s_red[8 + w] = b; }
    __syncthreads();
    if (threadIdx.x == 0) {
        float sa = 0.f, sb = 0.f;
#pragma unroll
        for (int i = 0; i < 8; i++) { sa += s_red[i]; sb += s_red[8 + i]; }
        s_red[16] = sa; s_red[17] = sb;
    }
    __syncthreads();
    return make_float2(s_red[16], s_red[17]);
}

// ---------------- split-K small-M GEMM phase ----------------
template <int PHASE>
__device__ void gemm_phase(int step, const float* __restrict__ W, float* s_mem) {
    constexpr int N   = (PHASE == 0) ? 1024 : ((PHASE == 1) ? 4096 : 3072);
    constexpr int K   = (PHASE == 0) ? 2048 : 4096;
    constexpr int NT  = (PHASE == 0) ? 128 : 256;
    constexpr int TN  = NT / 64;
    constexpr int NTILES = N / NT;
    constexpr int KSPL   = (PHASE == 0) ? 16 : 8;
    constexpr int KCH    = K / KSPL;

    int cta = blockIdx.x;
    if (cta >= NTILES * KSPL) return;
    int nt = cta % NTILES, ks = cta / NTILES;
    int tid = threadIdx.x;
    int b0 = (tid >> 6) * 8;
    int n0 = nt * NT + (tid & 63) * TN;
    const float* emb = g_emb + (size_t)step * (BB * NHID);

    float acc[8][TN];
#pragma unroll
    for (int i = 0; i < 8; i++)
#pragma unroll
        for (int j = 0; j < TN; j++) acc[i][j] = 0.f;

    const int kbase0 = ks * KCH;
    for (int kt = 0; kt < KCH; kt += 64) {
        int kb = kbase0 + kt;
#pragma unroll
        for (int r = 0; r < 8; r++) {
            int idx = tid + r * TPB;
            int bbx = idx >> 6, kk = idx & 63;
            int k = kb + kk;
            float v;
            if (PHASE == 0)
                v = (k < 1024) ? __ldg(&emb[bbx * 1024 + k]) : __ldcg(&g_xi[bbx * 4096 + 2048 + k]);
            else if (PHASE == 1)
                v = (k < 1024) ? __ldg(&emb[bbx * 1024 + k]) : __ldcg(&g_xi[bbx * 4096 + k]);
            else
                v = __ldcg(&g_inter[bbx * 4096 + k]);
            s_mem[kk * 36 + bbx] = v;
        }
        __syncthreads();
#pragma unroll
        for (int kk = 0; kk < 64; kk += 4) {
            float4 wv[TN];
#pragma unroll
            for (int j = 0; j < TN; j++)
                wv[j] = __ldg((const float4*)(W + (size_t)(n0 + j) * K + kb + kk));
#pragma unroll
            for (int c = 0; c < 4; c++) {
                float4 xa = *(const float4*)&s_mem[(kk + c) * 36 + b0];
                float4 xb = *(const float4*)&s_mem[(kk + c) * 36 + b0 + 4];
                float xs[8] = {xa.x, xa.y, xa.z, xa.w, xb.x, xb.y, xb.z, xb.w};
#pragma unroll
                for (int i = 0; i < 8; i++)
#pragma unroll
                    for (int j = 0; j < TN; j++)
                        acc[i][j] += xs[i] * (&wv[j].x)[c];
            }
        }
        __syncthreads();
    }
#pragma unroll
    for (int i = 0; i < 8; i++)
#pragma unroll
        for (int j = 0; j < TN; j++)
            g_part[(size_t)(ks * BB + b0 + i) * N + n0 + j] = acc[i][j];
}

// ---------------- fused split-K reduce + bias + LayerNorm + ReLU ----------------
template <int PHASE>
__device__ void ln_phase(int step, const float* __restrict__ bias,
                         const float* __restrict__ gam, const float* __restrict__ bet,
                         float* __restrict__ states_out, float* s_mem) {
    constexpr int N = (PHASE == 0) ? 1024 : ((PHASE == 1) ? 4096 : 3072);
    constexpr int KSPL = (PHASE == 0) ? 16 : 8;
    int b = blockIdx.x;
    if (b >= BB) return;
    int tid = threadIdx.x;
    float* s_red = s_mem + 4096;

    float lsum = 0.f, lsq = 0.f;
    for (int n = tid; n < N; n += TPB) {
        float v = __ldg(&bias[n]);
#pragma unroll
        for (int ks = 0; ks < KSPL; ks++)
            v += __ldcg(&g_part[(size_t)(ks * BB + b) * N + n]);
        s_mem[n] = v;
        lsum += v; lsq += v * v;
    }
    float2 r = blk_reduce2(lsum, lsq, s_red);
    float mu = r.x / (float)N;
    float var = r.y / (float)N - mu * mu;
    float rstd = rsqrtf(var + 1e-5f);

    for (int n = tid; n < N; n += TPB) {
        float v = (s_mem[n] - mu) * rstd * __ldg(&gam[n]) + __ldg(&bet[n]);
        v = fmaxf(v, 0.f);
        if (PHASE == 0) {
            g_xi[b * 4096 + 1024 + n] = v;
        } else if (PHASE == 1) {
            g_inter[b * 4096 + n] = v;
        } else {
            if (n < 1024)
                g_keys[((size_t)(step + 1) * BB + b) * NHID + n] = v;
            else if (n < 2048)
                g_vals[((size_t)(step + 1) * BB + b) * NHID + (n - 1024)] = v;
            else {
                g_xi[b * 4096 + 3072 + (n - 2048)] = v;
                states_out[((size_t)(step + 1) * BB + b) * NHID + (n - 2048)] = v;
            }
        }
    }
}

// ---------------- attention: one warp per (b, head) pair ----------------
__device__ void attn_phase(int step, float* s_mem) {
    int wid = (blockIdx.x << 3) + (threadIdx.x >> 5);
    int lane = threadIdx.x & 31;
    if (wid >= BB * NHEADS) return;
    int b = wid >> 4, n = wid & 15;

    const float* qp = &g_xi[b * 4096 + 1024 + n * 64];
    float4 qv[16];
#pragma unroll
    for (int t = 0; t < 16; t++) qv[t] = __ldcg((const float4*)(qp + t * 4));

    int cnt = step + 1;
    float sc[5];
#pragma unroll
    for (int t = 0; t < 5; t++) sc[t] = -1e30f;
    for (int t = 0; t < 5; t++) {
        int c = lane + t * 32;
        if (c < cnt) {
            const float* kp = &g_keys[((size_t)c * BB + b) * NHID + n * 64];
            float d = 0.f;
#pragma unroll
            for (int u = 0; u < 16; u++) {
                float4 kv = __ldcg((const float4*)(kp + u * 4));
                d += qv[u].x * kv.x + qv[u].y * kv.y + qv[u].z * kv.z + qv[u].w * kv.w;
            }
            sc[t] = d * 0.125f;
        }
    }
    float m = sc[0];
#pragma unroll
    for (int t = 1; t < 5; t++) m = fmaxf(m, sc[t]);
#pragma unroll
    for (int o = 16; o > 0; o >>= 1) m = fmaxf(m, __shfl_xor_sync(0xffffffffu, m, o));
    float p[5]; float lsum = 0.f;
    for (int t = 0; t < 5; t++) {
        int c = lane + t * 32;
        p[t] = (c < cnt) ? __expf(sc[t] - m) : 0.f;
        lsum += p[t];
    }
#pragma unroll
    for (int o = 16; o > 0; o >>= 1) lsum += __shfl_xor_sync(0xffffffffu, lsum, o);
    float inv = 1.f / lsum;
    float* sw = s_mem + (threadIdx.x >> 5) * 132;
    for (int t = 0; t < 5; t++) {
        int c = lane + t * 32;
        if (c < cnt) sw[c] = p[t] * inv;
    }
    __syncwarp();

    float a0 = 0.f, a1 = 0.f;
    for (int c = 0; c < cnt; c++) {
        float w = sw[c];
        const float* vp = &g_vals[((size_t)c * BB + b) * NHID + n * 64];
        a0 += w * __ldcg(vp + lane);
        a1 += w * __ldcg(vp + lane + 32);
    }
    g_xi[b * 4096 + 2048 + n * 64 + lane] = a0;
    g_xi[b * 4096 + 2048 + n * 64 + lane + 32] = a1;
}

// ---------------- persistent recurrence kernel ----------------
__global__ void __launch_bounds__(TPB, 1) rnn_kernel(
    const float* __restrict__ q_w, const float* __restrict__ q_b,
    const float* __restrict__ qn_g, const float* __restrict__ qn_b,
    const float* __restrict__ int_w, const float* __restrict__ int_b,
    const float* __restrict__ intn_g, const float* __restrict__ intn_b,
    const float* __restrict__ fin_w, const float* __restrict__ fin_b,
    const float* __restrict__ fn_g, const float* __restrict__ fn_b,
    float* __restrict__ states_out) {
    __shared__ __align__(16) float s_mem[4160];
    for (int step = 0; step < S_LEN; step++) {
        gemm_phase<0>(step, q_w, s_mem);                                  gbar();
        ln_phase<0>(step, q_b, qn_g, qn_b, nullptr, s_mem);               gbar();
        attn_phase(step, s_mem);                                          gbar();
        gemm_phase<1>(step, int_w, s_mem);                                gbar();
        ln_phase<1>(step, int_b, intn_g, intn_b, nullptr, s_mem);         gbar();
        gemm_phase<2>(step, fin_w, s_mem);                                gbar();
        ln_phase<2>(step, fin_b, fn_g, fn_b, states_out, s_mem);          gbar();
    }
}

// ---------------- embedding gather ----------------
__global__ void embed_kernel(const int* __restrict__ obs, const float* __restrict__ enc_w) {
    int r = blockIdx.x;
    int tok = __ldg(&obs[r]);
    const float4* src = (const float4*)(enc_w + (size_t)tok * NHID);
    float4* dst = (float4*)(g_emb + (size_t)r * NHID);
    dst[threadIdx.x] = __ldg(&src[threadIdx.x]);
}

// ---------------- init ----------------
__global__ void init_kernel(const float* __restrict__ h0, const float* __restrict__ kc,
                            const float* __restrict__ vc, float* __restrict__ states_out) {
    int b = blockIdx.x;
    int t = threadIdx.x;
    const float4* k4 = (const float4*)(kc + (size_t)b * NHID);
    const float4* v4 = (const float4*)(vc + (size_t)b * NHID);
    const float4* h4 = (const float4*)(h0 + (size_t)b * NHID);
    ((float4*)(g_keys + (size_t)b * NHID))[t] = k4[t];
    ((float4*)(g_vals + (size_t)b * NHID))[t] = v4[t];
    float4 hv = h4[t];
    ((float4*)(g_xi + (size_t)b * 4096 + 3072))[t] = hv;
    ((float4*)(states_out + (size_t)b * NHID))[t] = hv;
}

// ================= bf16x3 split conversion =================
__device__ __forceinline__ void split4(float4 v, __nv_bfloat16* hp, __nv_bfloat16* lp) {
    union { __nv_bfloat16 b[4]; uint2 u; } H, L;
    H.b[0] = __float2bfloat16_rn(v.x); L.b[0] = __float2bfloat16_rn(v.x - __bfloat162float(H.b[0]));
    H.b[1] = __float2bfloat16_rn(v.y); L.b[1] = __float2bfloat16_rn(v.y - __bfloat162float(H.b[1]));
    H.b[2] = __float2bfloat16_rn(v.z); L.b[2] = __float2bfloat16_rn(v.z - __bfloat162float(H.b[2]));
    H.b[3] = __float2bfloat16_rn(v.w); L.b[3] = __float2bfloat16_rn(v.w - __bfloat162float(H.b[3]));
    *(uint2*)hp = H.u;
    *(uint2*)lp = L.u;
}

__global__ void convert_w_kernel(const float* __restrict__ w) {
    size_t i = ((size_t)blockIdx.x * 256 + threadIdx.x) * 4;
    float4 v = __ldg((const float4*)(w + i));
    split4(v, g_whi + i, g_wlo + i);
}

__global__ void convert_a_kernel(const float* __restrict__ a) {
    size_t i = ((size_t)blockIdx.x * 256 + threadIdx.x) * 4;
    float4 v = __ldg((const float4*)(a + i));
    split4(v, g_ahi + i, g_alo + i);
}

// ================= HMMA (mma.sync) decoder GEMM =================
// D[4096, 32000] = A[4096,1024] @ W[32000,1024]^T  via bf16x3 split.
// CTA tile 128x128, 8 warps (2 m-warps x 4 n-warps), warp tile 64x32.
// K staged in chunks of 64 via cp.async.cg, double-buffered (2 x 64KB smem).
#define DM 128
#define DN 128
#define DKC 64
#define NKCH 16
#define BUF_BYTES 65536
#define T_AHI 0
#define T_ALO 16384
#define T_WHI 32768
#define T_WLO 49152

__device__ __forceinline__ uint32_t smem_u32(const void* p) {
    uint32_t a;
    asm("{ .reg .u64 t; cvta.to.shared.u64 t, %1; cvt.u32.u64 %0, t; }" : "=r"(a) : "l"(p));
    return a;
}
__device__ __forceinline__ void cpa16(uint32_t dst, const void* src) {
    asm volatile("cp.async.cg.shared.global [%0], [%1], 16;" :: "r"(dst), "l"(src));
}
__device__ __forceinline__ void cpa_commit() {
    asm volatile("cp.async.commit_group;" ::: "memory");
}
__device__ __forceinline__ void ldsm4(uint32_t* r, uint32_t addr) {
    asm volatile("ldmatrix.sync.aligned.m8n8.x4.shared.b16 {%0,%1,%2,%3}, [%4];"
                 : "=r"(r[0]), "=r"(r[1]), "=r"(r[2]), "=r"(r[3]) : "r"(addr));
}
__device__ __forceinline__ void mma16816(float* d, const uint32_t* a, const uint32_t* b) {
    asm volatile(
        "mma.sync.aligned.m16n8k16.row.col.f32.bf16.bf16.f32 "
        "{%0,%1,%2,%3}, {%4,%5,%6,%7}, {%8,%9}, {%0,%1,%2,%3};"
        : "+f"(d[0]), "+f"(d[1]), "+f"(d[2]), "+f"(d[3])
        : "r"(a[0]), "r"(a[1]), "r"(a[2]), "r"(a[3]), "r"(b[0]), "r"(b[1]));
}

__global__ void __launch_bounds__(256, 1) dec_mma_kernel(const float* __restrict__ bias,
                                                         float* __restrict__ out) {
    extern __shared__ __align__(1024) char smem[];
    const uint32_t sb = smem_u32(smem);
    const int tid = threadIdx.x;
    const int wid = tid >> 5, lane = tid & 31;
    const int warp_m = wid & 1, warp_n = wid >> 1;
    const size_t m0 = (size_t)blockIdx.x * DM;
    const size_t n0 = (size_t)blockIdx.y * DN;

    // ---- cp.async chunk issue: 4096 x 16B ops, 16 per thread ----
    auto issue = [&](int ch, int buf) {
        const uint32_t base = sb + buf * BUF_BYTES;
        const int kb = ch * DKC;
#pragma unroll
        for (int i = 0; i < 4; i++) {
            int idx = tid + i * 256;        // 0..1023
            int r = idx >> 3, u = idx & 7;  // row, 16B k-unit
            uint32_t so = (uint32_t)(r * 128 + ((u ^ (r & 7)) << 4));
            size_t goA = (m0 + r) * 1024 + kb + u * 8;
            size_t goW = (n0 + r) * 1024 + kb + u * 8;
            cpa16(base + T_AHI + so, g_ahi + goA);
            cpa16(base + T_ALO + so, g_alo + goA);
            cpa16(base + T_WHI + so, g_whi + goW);
            cpa16(base + T_WLO + so, g_wlo + goW);
        }
        cpa_commit();
    };

    float acc[4][4][4];
#pragma unroll
    for (int mt = 0; mt < 4; mt++)
#pragma unroll
        for (int nt = 0; nt < 4; nt++)
#pragma unroll
            for (int r = 0; r < 4; r++) acc[mt][nt][r] = 0.f;

    issue(0, 0);

    // Fragment address components (constant across chunks except base/unit)
    // A: matrix j = lane>>3: row_local = (j&1)*8 + (lane&7), unit += (j>>1)
    const int a_rl = ((lane >> 3) & 1) * 8 + (lane & 7);
    const int a_ub = (lane >> 4);          // 0 or 1
    // B: matrix j: n_local = (j>>1)*8 + (lane&7), unit += (j&1)
    const int b_rl = ((lane >> 4)) * 8 + (lane & 7);
    const int b_ub = ((lane >> 3) & 1);

    for (int ch = 0; ch < NKCH; ch++) {
        if (ch + 1 < NKCH) {
            issue(ch + 1, (ch + 1) & 1);
            asm volatile("cp.async.wait_group 1;" ::: "memory");
        } else {
            asm volatile("cp.async.wait_group 0;" ::: "memory");
        }
        __syncthreads();
        const uint32_t base = sb + (ch & 1) * BUF_BYTES;

#pragma unroll
        for (int s = 0; s < 4; s++) {
            uint32_t ahi[4][4], alo[4][4];
#pragma unroll
            for (int mt = 0; mt < 4; mt++) {
                int row = warp_m * 64 + mt * 16 + a_rl;
                int unit = s * 2 + a_ub;
                uint32_t off = (uint32_t)(row * 128 + ((unit ^ (row & 7)) << 4));
                ldsm4(ahi[mt], base + T_AHI + off);
                ldsm4(alo[mt], base + T_ALO + off);
            }
            uint32_t bhi[4][2], blo[4][2];
#pragma unroll
            for (int p = 0; p < 2; p++) {
                int row = warp_n * 32 + p * 16 + b_rl;
                int unit = s * 2 + b_ub;
                uint32_t off = (uint32_t)(row * 128 + ((unit ^ (row & 7)) << 4));
                uint32_t t4[4];
                ldsm4(t4, base + T_WHI + off);
                bhi[p * 2][0] = t4[0]; bhi[p * 2][1] = t4[1];
                bhi[p * 2 + 1][0] = t4[2]; bhi[p * 2 + 1][1] = t4[3];
                ldsm4(t4, base + T_WLO + off);
                blo[p * 2][0] = t4[0]; blo[p * 2][1] = t4[1];
                blo[p * 2 + 1][0] = t4[2]; blo[p * 2 + 1][1] = t4[3];
            }
#pragma unroll
            for (int mt = 0; mt < 4; mt++)
#pragma unroll
                for (int nt = 0; nt < 4; nt++) {
                    mma16816(acc[mt][nt], ahi[mt], bhi[nt]);
                    mma16816(acc[mt][nt], ahi[mt], blo[nt]);
                    mma16816(acc[mt][nt], alo[mt], bhi[nt]);
                }
        }
        __syncthreads();
    }

    // ---- epilogue: d regs -> out + bias ----
#pragma unroll
    for (int nt = 0; nt < 4; nt++) {
        size_t n = n0 + warp_n * 32 + nt * 8 + (lane & 3) * 2;
        float2 bv = *(const float2*)(bias + n);
#pragma unroll
        for (int mt = 0; mt < 4; mt++) {
            size_t m = m0 + warp_m * 64 + mt * 16 + (lane >> 2);
            float2 o0 = make_float2(acc[mt][nt][0] + bv.x, acc[mt][nt][1] + bv.y);
            float2 o1 = make_float2(acc[mt][nt][2] + bv.x, acc[mt][nt][3] + bv.y);
            *(float2*)(out + m * VOC + n) = o0;
            *(float2*)(out + (m + 8) * VOC + n) = o1;
        }
    }
}

extern "C" void kernel_launch(void* const* d_in, const int* in_sizes, int n_in,
                              void* d_out, int out_size) {
    const int*   obs    = (const int*)d_in[0];
    const float* h0     = (const float*)d_in[1];
    const float* kc     = (const float*)d_in[2];
    const float* vc     = (const float*)d_in[3];
    const float* enc_w  = (const float*)d_in[4];
    const float* q_w    = (const float*)d_in[5];
    const float* q_b    = (const float*)d_in[6];
    const float* qn_g   = (const float*)d_in[7];
    const float* qn_b   = (const float*)d_in[8];
    const float* int_w  = (const float*)d_in[9];
    const float* int_b  = (const float*)d_in[10];
    const float* intn_g = (const float*)d_in[11];
    const float* intn_b = (const float*)d_in[12];
    const float* fin_w  = (const float*)d_in[13];
    const float* fin_b  = (const float*)d_in[14];
    const float* fn_g   = (const float*)d_in[15];
    const float* fn_b   = (const float*)d_in[16];
    const float* dec_w  = (const float*)d_in[17];
    const float* dec_b  = (const float*)d_in[18];

    float* out = (float*)d_out;
    float* states_full = out + (size_t)S_LEN * BB * VOC;  // [S+1][B][NHID]

    init_kernel<<<BB, 256>>>(h0, kc, vc, states_full);
    embed_kernel<<<S_LEN * BB, 256>>>(obs, enc_w);
    convert_w_kernel<<<(VOC * NHID) / 1024, 256>>>(dec_w);
    rnn_kernel<<<NCTA, TPB>>>(q_w, q_b, qn_g, qn_b, int_w, int_b, intn_g, intn_b,
                              fin_w, fin_b, fn_g, fn_b, states_full);
    convert_a_kernel<<<(S_LEN * BB * NHID) / 1024, 256>>>(states_full + (size_t)BB * NHID);
    cudaFuncSetAttribute(dec_mma_kernel, cudaFuncAttributeMaxDynamicSharedMemorySize, 2 * BUF_BYTES);
    dec_mma_kernel<<<dim3((S_LEN * BB) / DM, VOC / DN), 256, 2 * BUF_BYTES>>>(dec_b, out);
}

// round 6
// speedup vs baseline: 3.1268x; 2.6957x over previous
#include <cuda_runtime.h>
#include <cuda_bf16.h>
#include <cstdint>

#define S_LEN 128
#define BB 32
#define VOC 32000
#define NHID 1024
#define NHEADS 16
#define HD 64
#define NCTA 128
#define TPB 256

// ---------------- device scratch (no allocations allowed) ----------------
__device__ float g_keys[(S_LEN + 1) * BB * NHID];
__device__ float g_vals[(S_LEN + 1) * BB * NHID];
__device__ float g_emb[S_LEN * BB * NHID];
__device__ float g_xi[BB * 4 * NHID];     // fp32, only q section [1024:2048) used
__device__ float g_part[16 * BB * 4096];  // split-K partials
__device__ unsigned g_bar;                // monotonic grid-barrier counter

// bf16 hi/lo activations
__device__ __nv_bfloat16 g_xh[BB * 4 * NHID];   // [b][ e(virt) | q | attn | hidden ]
__device__ __nv_bfloat16 g_xl[BB * 4 * NHID];
__device__ __nv_bfloat16 g_ih[BB * 4 * NHID];   // inter
__device__ __nv_bfloat16 g_il[BB * 4 * NHID];
__device__ __nv_bfloat16 g_eh[S_LEN * BB * NHID];
__device__ __nv_bfloat16 g_el[S_LEN * BB * NHID];

// bf16 hi/lo recurrence weights
__device__ __nv_bfloat16 g_qwh[NHID * 2 * NHID];
__device__ __nv_bfloat16 g_qwl[NHID * 2 * NHID];
__device__ __nv_bfloat16 g_iwh[(size_t)4 * NHID * 4 * NHID];
__device__ __nv_bfloat16 g_iwl[(size_t)4 * NHID * 4 * NHID];
__device__ __nv_bfloat16 g_fwh[(size_t)3 * NHID * 4 * NHID];
__device__ __nv_bfloat16 g_fwl[(size_t)3 * NHID * 4 * NHID];

// bf16 hi/lo decoder operands
__device__ __nv_bfloat16 g_whi[(size_t)VOC * NHID];
__device__ __nv_bfloat16 g_wlo[(size_t)VOC * NHID];
__device__ __nv_bfloat16 g_ahi[(size_t)S_LEN * BB * NHID];
__device__ __nv_bfloat16 g_alo[(size_t)S_LEN * BB * NHID];

// ---------------- common helpers ----------------
__device__ __forceinline__ uint32_t smem_u32(const void* p) {
    uint32_t a;
    asm("{ .reg .u64 t; cvta.to.shared.u64 t, %1; cvt.u32.u64 %0, t; }" : "=r"(a) : "l"(p));
    return a;
}
__device__ __forceinline__ void cpa16(uint32_t dst, const void* src) {
    asm volatile("cp.async.cg.shared.global [%0], [%1], 16;" :: "r"(dst), "l"(src));
}
__device__ __forceinline__ void cpa_commit() {
    asm volatile("cp.async.commit_group;" ::: "memory");
}
__device__ __forceinline__ void ldsm4(uint32_t* r, uint32_t addr) {
    asm volatile("ldmatrix.sync.aligned.m8n8.x4.shared.b16 {%0,%1,%2,%3}, [%4];"
                 : "=r"(r[0]), "=r"(r[1]), "=r"(r[2]), "=r"(r[3]) : "r"(addr));
}
__device__ __forceinline__ void mma16816(float* d, const uint32_t* a, const uint32_t* b) {
    asm volatile(
        "mma.sync.aligned.m16n8k16.row.col.f32.bf16.bf16.f32 "
        "{%0,%1,%2,%3}, {%4,%5,%6,%7}, {%8,%9}, {%0,%1,%2,%3};"
        : "+f"(d[0]), "+f"(d[1]), "+f"(d[2]), "+f"(d[3])
        : "r"(a[0]), "r"(a[1]), "r"(a[2]), "r"(a[3]), "r"(b[0]), "r"(b[1]));
}
__device__ __forceinline__ void split1(float v, __nv_bfloat16* h, __nv_bfloat16* l) {
    __nv_bfloat16 hh = __float2bfloat16_rn(v);
    *h = hh;
    *l = __float2bfloat16_rn(v - __bfloat162float(hh));
}
__device__ __forceinline__ void split4(float4 v, __nv_bfloat16* hp, __nv_bfloat16* lp) {
    union { __nv_bfloat16 b[4]; uint2 u; } H, L;
    H.b[0] = __float2bfloat16_rn(v.x); L.b[0] = __float2bfloat16_rn(v.x - __bfloat162float(H.b[0]));
    H.b[1] = __float2bfloat16_rn(v.y); L.b[1] = __float2bfloat16_rn(v.y - __bfloat162float(H.b[1]));
    H.b[2] = __float2bfloat16_rn(v.z); L.b[2] = __float2bfloat16_rn(v.z - __bfloat162float(H.b[2]));
    H.b[3] = __float2bfloat16_rn(v.w); L.b[3] = __float2bfloat16_rn(v.w - __bfloat162float(H.b[3]));
    *(uint2*)hp = H.u;
    *(uint2*)lp = L.u;
}

// ---------------- grid barrier (monotonic; replay-safe) ----------------
__device__ __forceinline__ void gbar() {
    __threadfence();
    __syncthreads();
    if (threadIdx.x == 0) {
        unsigned a = atomicAdd(&g_bar, 1u) + 1u;
        unsigned target = ((a + NCTA - 1u) / NCTA) * NCTA;
        while (*(volatile unsigned*)&g_bar < target) { __nanosleep(32); }
        __threadfence();
    }
    __syncthreads();
}

// ---------------- block reduce (sum, sumsq) ----------------
__device__ float2 blk_reduce2(float a, float b, float* s_red) {
#pragma unroll
    for (int o = 16; o > 0; o >>= 1) {
        a += __shfl_xor_sync(0xffffffffu, a, o);
        b += __shfl_xor_sync(0xffffffffu, b, o);
    }
    int w = threadIdx.x >> 5, l = threadIdx.x & 31;
    if (l == 0) { s_red[w] = a; s_red[8 + w] = b; }
    __syncthreads();
    if (threadIdx.x == 0) {
        float sa = 0.f, sb = 0.f;
#pragma unroll
        for (int i = 0; i < 8; i++) { sa += s_red[i]; sb += s_red[8 + i]; }
        s_red[16] = sa; s_red[17] = sb;
    }
    __syncthreads();
    return make_float2(s_red[16], s_red[17]);
}

// ================= recurrence HMMA GEMM phase (bf16x3) =================
// PHASE 0: q   [32][1024], K=2048, x=[emb|hidden],        NTILES=8,  KSPL=16
// PHASE 1: int [32][4096], K=4096, x=[emb|q|attn|hidden], NTILES=32, KSPL=4
// PHASE 2: fin [32][3072], K=4096, x=inter,               NTILES=24, KSPL=4
// smem buffer layout (per buffer, 40960 B): AHI 4KB | ALO 4KB | WHI 16KB | WLO 16KB
#define RBUF 40960
#define R_AHI 0
#define R_ALO 4096
#define R_WHI 8192
#define R_WLO 24576

template <int PHASE>
__device__ void gemm_hmma(int step, const __nv_bfloat16* __restrict__ Wh,
                          const __nv_bfloat16* __restrict__ Wl, char* smem) {
    constexpr int N      = (PHASE == 0) ? 1024 : ((PHASE == 1) ? 4096 : 3072);
    constexpr int K      = (PHASE == 0) ? 2048 : 4096;
    constexpr int NTILES = N / 128;
    constexpr int KSPL   = (PHASE == 0) ? 16 : 4;
    constexpr int KC     = K / KSPL;
    constexpr int NCH    = KC / 64;

    const int cta = blockIdx.x;
    if (cta >= NTILES * KSPL) return;
    const int ntile = cta % NTILES, ks = cta / NTILES;
    const int n0 = ntile * 128;
    const int k0 = ks * KC;
    const uint32_t sb = smem_u32(smem);
    const int tid = threadIdx.x, wid = tid >> 5, lane = tid & 31;

    const __nv_bfloat16* eh = g_eh + (size_t)step * (BB * NHID);
    const __nv_bfloat16* el = g_el + (size_t)step * (BB * NHID);

    auto issue = [&](int ch, int buf) {
        const uint32_t base = sb + buf * RBUF;
        const int kb = k0 + ch * 64;
        // W: 128 rows x 8 units, hi+lo
#pragma unroll
        for (int i = 0; i < 4; i++) {
            int idx = tid + i * 256;
            int r = idx >> 3, u = idx & 7;
            uint32_t so = (uint32_t)(r * 128 + ((u ^ (r & 7)) << 4));
            size_t go = (size_t)(n0 + r) * K + kb + u * 8;
            cpa16(base + R_WHI + so, Wh + go);
            cpa16(base + R_WLO + so, Wl + go);
        }
        // A: 32 rows x 8 units, hi+lo (1 op each per thread)
        {
            int r = tid >> 3, u = tid & 7;
            int k = kb + u * 8;
            uint32_t so = (uint32_t)(r * 128 + ((u ^ (r & 7)) << 4));
            const __nv_bfloat16 *sh, *sl;
            if (PHASE == 0) {
                if (k < 1024) { sh = eh + r * 1024 + k; sl = el + r * 1024 + k; }
                else { sh = g_xh + r * 4096 + 2048 + k; sl = g_xl + r * 4096 + 2048 + k; }
            } else if (PHASE == 1) {
                if (k < 1024) { sh = eh + r * 1024 + k; sl = el + r * 1024 + k; }
                else { sh = g_xh + r * 4096 + k; sl = g_xl + r * 4096 + k; }
            } else {
                sh = g_ih + r * 4096 + k; sl = g_il + r * 4096 + k;
            }
            cpa16(base + R_AHI + so, sh);
            cpa16(base + R_ALO + so, sl);
        }
        cpa_commit();
    };

    float acc[2][2][4];
#pragma unroll
    for (int mt = 0; mt < 2; mt++)
#pragma unroll
        for (int nt = 0; nt < 2; nt++)
#pragma unroll
            for (int r = 0; r < 4; r++) acc[mt][nt][r] = 0.f;

    issue(0, 0);

    const int a_rl = ((lane >> 3) & 1) * 8 + (lane & 7);
    const int a_ub = (lane >> 4);
    const int b_rl = ((lane >> 4)) * 8 + (lane & 7);
    const int b_ub = ((lane >> 3) & 1);

    for (int ch = 0; ch < NCH; ch++) {
        if (ch + 1 < NCH) {
            issue(ch + 1, (ch + 1) & 1);
            asm volatile("cp.async.wait_group 1;" ::: "memory");
        } else {
            asm volatile("cp.async.wait_group 0;" ::: "memory");
        }
        __syncthreads();
        const uint32_t base = sb + (ch & 1) * RBUF;

#pragma unroll
        for (int s = 0; s < 4; s++) {
            uint32_t ahi[2][4], alo[2][4];
#pragma unroll
            for (int mt = 0; mt < 2; mt++) {
                int row = mt * 16 + a_rl;
                int unit = s * 2 + a_ub;
                uint32_t off = (uint32_t)(row * 128 + ((unit ^ (row & 7)) << 4));
                ldsm4(ahi[mt], base + R_AHI + off);
                ldsm4(alo[mt], base + R_ALO + off);
            }
            uint32_t bhi[2][2], blo[2][2];
            {
                int row = wid * 16 + b_rl;
                int unit = s * 2 + b_ub;
                uint32_t off = (uint32_t)(row * 128 + ((unit ^ (row & 7)) << 4));
                uint32_t t4[4];
                ldsm4(t4, base + R_WHI + off);
                bhi[0][0] = t4[0]; bhi[0][1] = t4[1]; bhi[1][0] = t4[2]; bhi[1][1] = t4[3];
                ldsm4(t4, base + R_WLO + off);
                blo[0][0] = t4[0]; blo[0][1] = t4[1]; blo[1][0] = t4[2]; blo[1][1] = t4[3];
            }
#pragma unroll
            for (int mt = 0; mt < 2; mt++)
#pragma unroll
                for (int nt = 0; nt < 2; nt++) {
                    mma16816(acc[mt][nt], ahi[mt], bhi[nt]);
                    mma16816(acc[mt][nt], ahi[mt], blo[nt]);
                    mma16816(acc[mt][nt], alo[mt], bhi[nt]);
                }
        }
        __syncthreads();
    }

    // partial store: fp32 to g_part[ks][m][N]
#pragma unroll
    for (int mt = 0; mt < 2; mt++) {
        int m = mt * 16 + (lane >> 2);
#pragma unroll
        for (int nt = 0; nt < 2; nt++) {
            int n = n0 + wid * 16 + nt * 8 + (lane & 3) * 2;
            *(float2*)&g_part[(size_t)(ks * BB + m) * N + n] =
                make_float2(acc[mt][nt][0], acc[mt][nt][1]);
            *(float2*)&g_part[(size_t)(ks * BB + m + 8) * N + n] =
                make_float2(acc[mt][nt][2], acc[mt][nt][3]);
        }
    }
}

// ---------------- fused split-K reduce + bias + LayerNorm + ReLU ----------------
template <int PHASE>
__device__ void ln_phase(int step, const float* __restrict__ bias,
                         const float* __restrict__ gam, const float* __restrict__ bet,
                         float* __restrict__ states_out, float* s_mem) {
    constexpr int N = (PHASE == 0) ? 1024 : ((PHASE == 1) ? 4096 : 3072);
    constexpr int KSPL = (PHASE == 0) ? 16 : 4;
    int b = blockIdx.x;
    if (b >= BB) return;
    int tid = threadIdx.x;
    float* s_red = s_mem + 4096;

    float lsum = 0.f, lsq = 0.f;
    for (int n = tid; n < N; n += TPB) {
        float v = __ldg(&bias[n]);
#pragma unroll
        for (int ks = 0; ks < KSPL; ks++)
            v += __ldcg(&g_part[(size_t)(ks * BB + b) * N + n]);
        s_mem[n] = v;
        lsum += v; lsq += v * v;
    }
    float2 r = blk_reduce2(lsum, lsq, s_red);
    float mu = r.x / (float)N;
    float var = r.y / (float)N - mu * mu;
    float rstd = rsqrtf(var + 1e-5f);

    for (int n = tid; n < N; n += TPB) {
        float v = (s_mem[n] - mu) * rstd * __ldg(&gam[n]) + __ldg(&bet[n]);
        v = fmaxf(v, 0.f);
        if (PHASE == 0) {
            g_xi[b * 4096 + 1024 + n] = v;  // fp32 q for attention
            split1(v, &g_xh[b * 4096 + 1024 + n], &g_xl[b * 4096 + 1024 + n]);
        } else if (PHASE == 1) {
            split1(v, &g_ih[b * 4096 + n], &g_il[b * 4096 + n]);
        } else {
            if (n < 1024)
                g_keys[((size_t)(step + 1) * BB + b) * NHID + n] = v;
            else if (n < 2048)
                g_vals[((size_t)(step + 1) * BB + b) * NHID + (n - 1024)] = v;
            else {
                int nn = n - 2048;
                split1(v, &g_xh[b * 4096 + 3072 + nn], &g_xl[b * 4096 + 3072 + nn]);
                states_out[((size_t)(step + 1) * BB + b) * NHID + nn] = v;
            }
        }
    }
}

// ---------------- attention: one warp per (b, head) pair ----------------
__device__ void attn_phase(int step, float* s_mem) {
    int wid = (blockIdx.x << 3) + (threadIdx.x >> 5);
    int lane = threadIdx.x & 31;
    if (wid >= BB * NHEADS) return;
    int b = wid >> 4, n = wid & 15;

    const float* qp = &g_xi[b * 4096 + 1024 + n * 64];
    float4 qv[16];
#pragma unroll
    for (int t = 0; t < 16; t++) qv[t] = __ldcg((const float4*)(qp + t * 4));

    int cnt = step + 1;
    float sc[5];
#pragma unroll
    for (int t = 0; t < 5; t++) sc[t] = -1e30f;
    for (int t = 0; t < 5; t++) {
        int c = lane + t * 32;
        if (c < cnt) {
            const float* kp = &g_keys[((size_t)c * BB + b) * NHID + n * 64];
            float d = 0.f;
#pragma unroll
            for (int u = 0; u < 16; u++) {
                float4 kv = __ldcg((const float4*)(kp + u * 4));
                d += qv[u].x * kv.x + qv[u].y * kv.y + qv[u].z * kv.z + qv[u].w * kv.w;
            }
            sc[t] = d * 0.125f;
        }
    }
    float m = sc[0];
#pragma unroll
    for (int t = 1; t < 5; t++) m = fmaxf(m, sc[t]);
#pragma unroll
    for (int o = 16; o > 0; o >>= 1) m = fmaxf(m, __shfl_xor_sync(0xffffffffu, m, o));
    float p[5]; float lsum = 0.f;
    for (int t = 0; t < 5; t++) {
        int c = lane + t * 32;
        p[t] = (c < cnt) ? __expf(sc[t] - m) : 0.f;
        lsum += p[t];
    }
#pragma unroll
    for (int o = 16; o > 0; o >>= 1) lsum += __shfl_xor_sync(0xffffffffu, lsum, o);
    float inv = 1.f / lsum;
    float* sw = s_mem + (threadIdx.x >> 5) * 132;
    for (int t = 0; t < 5; t++) {
        int c = lane + t * 32;
        if (c < cnt) sw[c] = p[t] * inv;
    }
    __syncwarp();

    float a0 = 0.f, a1 = 0.f;
    for (int c = 0; c < cnt; c++) {
        float w = sw[c];
        const float* vp = &g_vals[((size_t)c * BB + b) * NHID + n * 64];
        a0 += w * __ldcg(vp + lane);
        a1 += w * __ldcg(vp + lane + 32);
    }
    int o0 = b * 4096 + 2048 + n * 64 + lane;
    split1(a0, &g_xh[o0], &g_xl[o0]);
    split1(a1, &g_xh[o0 + 32], &g_xl[o0 + 32]);
}

// ---------------- persistent recurrence kernel ----------------
__global__ void __launch_bounds__(TPB, 1) rnn_kernel(
    const float* __restrict__ q_b,
    const float* __restrict__ qn_g, const float* __restrict__ qn_b,
    const float* __restrict__ int_b,
    const float* __restrict__ intn_g, const float* __restrict__ intn_b,
    const float* __restrict__ fin_b,
    const float* __restrict__ fn_g, const float* __restrict__ fn_b,
    float* __restrict__ states_out) {
    extern __shared__ __align__(1024) char dsm[];
    float* s_mem = (float*)dsm;
    for (int step = 0; step < S_LEN; step++) {
        gemm_hmma<0>(step, g_qwh, g_qwl, dsm);                    gbar();
        ln_phase<0>(step, q_b, qn_g, qn_b, nullptr, s_mem);       gbar();
        attn_phase(step, s_mem);                                  gbar();
        gemm_hmma<1>(step, g_iwh, g_iwl, dsm);                    gbar();
        ln_phase<1>(step, int_b, intn_g, intn_b, nullptr, s_mem); gbar();
        gemm_hmma<2>(step, g_fwh, g_fwl, dsm);                    gbar();
        ln_phase<2>(step, fin_b, fn_g, fn_b, states_out, s_mem);  gbar();
    }
}

// ---------------- embedding gather ----------------
__global__ void embed_kernel(const int* __restrict__ obs, const float* __restrict__ enc_w) {
    int r = blockIdx.x;
    int tok = __ldg(&obs[r]);
    const float4* src = (const float4*)(enc_w + (size_t)tok * NHID);
    float4* dst = (float4*)(g_emb + (size_t)r * NHID);
    dst[threadIdx.x] = __ldg(&src[threadIdx.x]);
}

// ---------------- init ----------------
__global__ void init_kernel(const float* __restrict__ h0, const float* __restrict__ kc,
                            const float* __restrict__ vc, float* __restrict__ states_out) {
    int b = blockIdx.x;
    int t = threadIdx.x;
    const float4* k4 = (const float4*)(kc + (size_t)b * NHID);
    const float4* v4 = (const float4*)(vc + (size_t)b * NHID);
    const float4* h4 = (const float4*)(h0 + (size_t)b * NHID);
    ((float4*)(g_keys + (size_t)b * NHID))[t] = k4[t];
    ((float4*)(g_vals + (size_t)b * NHID))[t] = v4[t];
    float4 hv = h4[t];
    split4(hv, &g_xh[b * 4096 + 3072 + t * 4], &g_xl[b * 4096 + 3072 + t * 4]);
    ((float4*)(states_out + (size_t)b * NHID))[t] = hv;
}

// ================= split conversion kernels =================
#define MK_SPLIT(NAME, HDST, LDST)                                                 \
    __global__ void NAME(const float* __restrict__ s) {                            \
        size_t i = ((size_t)blockIdx.x * 256 + threadIdx.x) * 4;                   \
        split4(__ldg((const float4*)(s + i)), (HDST) + i, (LDST) + i);             \
    }
MK_SPLIT(split_qw, g_qwh, g_qwl)
MK_SPLIT(split_iw, g_iwh, g_iwl)
MK_SPLIT(split_fw, g_fwh, g_fwl)
MK_SPLIT(split_decw, g_whi, g_wlo)
MK_SPLIT(split_states, g_ahi, g_alo)

__global__ void split_emb_kernel() {
    size_t i = ((size_t)blockIdx.x * 256 + threadIdx.x) * 4;
    split4(*(const float4*)(g_emb + i), g_eh + i, g_el + i);
}

// ================= HMMA decoder GEMM (validated in R4) =================
#define DM 128
#define DN 128
#define DKC 64
#define NKCH 16
#define BUF_BYTES 65536
#define T_AHI 0
#define T_ALO 16384
#define T_WHI 32768
#define T_WLO 49152

__global__ void __launch_bounds__(256, 1) dec_mma_kernel(const float* __restrict__ bias,
                                                         float* __restrict__ out) {
    extern __shared__ __align__(1024) char smem[];
    const uint32_t sb = smem_u32(smem);
    const int tid = threadIdx.x;
    const int wid = tid >> 5, lane = tid & 31;
    const int warp_m = wid & 1, warp_n = wid >> 1;
    const size_t m0 = (size_t)blockIdx.x * DM;
    const size_t n0 = (size_t)blockIdx.y * DN;

    auto issue = [&](int ch, int buf) {
        const uint32_t base = sb + buf * BUF_BYTES;
        const int kb = ch * DKC;
#pragma unroll
        for (int i = 0; i < 4; i++) {
            int idx = tid + i * 256;
            int r = idx >> 3, u = idx & 7;
            uint32_t so = (uint32_t)(r * 128 + ((u ^ (r & 7)) << 4));
            size_t goA = (m0 + r) * 1024 + kb + u * 8;
            size_t goW = (n0 + r) * 1024 + kb + u * 8;
            cpa16(base + T_AHI + so, g_ahi + goA);
            cpa16(base + T_ALO + so, g_alo + goA);
            cpa16(base + T_WHI + so, g_whi + goW);
            cpa16(base + T_WLO + so, g_wlo + goW);
        }
        cpa_commit();
    };

    float acc[4][4][4];
#pragma unroll
    for (int mt = 0; mt < 4; mt++)
#pragma unroll
        for (int nt = 0; nt < 4; nt++)
#pragma unroll
            for (int r = 0; r < 4; r++) acc[mt][nt][r] = 0.f;

    issue(0, 0);

    const int a_rl = ((lane >> 3) & 1) * 8 + (lane & 7);
    const int a_ub = (lane >> 4);
    const int b_rl = ((lane >> 4)) * 8 + (lane & 7);
    const int b_ub = ((lane >> 3) & 1);

    for (int ch = 0; ch < NKCH; ch++) {
        if (ch + 1 < NKCH) {
            issue(ch + 1, (ch + 1) & 1);
            asm volatile("cp.async.wait_group 1;" ::: "memory");
        } else {
            asm volatile("cp.async.wait_group 0;" ::: "memory");
        }
        __syncthreads();
        const uint32_t base = sb + (ch & 1) * BUF_BYTES;

#pragma unroll
        for (int s = 0; s < 4; s++) {
            uint32_t ahi[4][4], alo[4][4];
#pragma unroll
            for (int mt = 0; mt < 4; mt++) {
                int row = warp_m * 64 + mt * 16 + a_rl;
                int unit = s * 2 + a_ub;
                uint32_t off = (uint32_t)(row * 128 + ((unit ^ (row & 7)) << 4));
                ldsm4(ahi[mt], base + T_AHI + off);
                ldsm4(alo[mt], base + T_ALO + off);
            }
            uint32_t bhi[4][2], blo[4][2];
#pragma unroll
            for (int p = 0; p < 2; p++) {
                int row = warp_n * 32 + p * 16 + b_rl;
                int unit = s * 2 + b_ub;
                uint32_t off = (uint32_t)(row * 128 + ((unit ^ (row & 7)) << 4));
                uint32_t t4[4];
                ldsm4(t4, base + T_WHI + off);
                bhi[p * 2][0] = t4[0]; bhi[p * 2][1] = t4[1];
                bhi[p * 2 + 1][0] = t4[2]; bhi[p * 2 + 1][1] = t4[3];
                ldsm4(t4, base + T_WLO + off);
                blo[p * 2][0] = t4[0]; blo[p * 2][1] = t4[1];
                blo[p * 2 + 1][0] = t4[2]; blo[p * 2 + 1][1] = t4[3];
            }
#pragma unroll
            for (int mt = 0; mt < 4; mt++)
#pragma unroll
                for (int nt = 0; nt < 4; nt++) {
                    mma16816(acc[mt][nt], ahi[mt], bhi[nt]);
                    mma16816(acc[mt][nt], ahi[mt], blo[nt]);
                    mma16816(acc[mt][nt], alo[mt], bhi[nt]);
                }
        }
        __syncthreads();
    }

#pragma unroll
    for (int nt = 0; nt < 4; nt++) {
        size_t n = n0 + warp_n * 32 + nt * 8 + (lane & 3) * 2;
        float2 bv = *(const float2*)(bias + n);
#pragma unroll
        for (int mt = 0; mt < 4; mt++) {
            size_t m = m0 + warp_m * 64 + mt * 16 + (lane >> 2);
            float2 o0 = make_float2(acc[mt][nt][0] + bv.x, acc[mt][nt][1] + bv.y);
            float2 o1 = make_float2(acc[mt][nt][2] + bv.x, acc[mt][nt][3] + bv.y);
            *(float2*)(out + m * VOC + n) = o0;
            *(float2*)(out + (m + 8) * VOC + n) = o1;
        }
    }
}

extern "C" void kernel_launch(void* const* d_in, const int* in_sizes, int n_in,
                              void* d_out, int out_size) {
    const int*   obs    = (const int*)d_in[0];
    const float* h0     = (const float*)d_in[1];
    const float* kc     = (const float*)d_in[2];
    const float* vc     = (const float*)d_in[3];
    const float* enc_w  = (const float*)d_in[4];
    const float* q_w    = (const float*)d_in[5];
    const float* q_b    = (const float*)d_in[6];
    const float* qn_g   = (const float*)d_in[7];
    const float* qn_b   = (const float*)d_in[8];
    const float* int_w  = (const float*)d_in[9];
    const float* int_b  = (const float*)d_in[10];
    const float* intn_g = (const float*)d_in[11];
    const float* intn_b = (const float*)d_in[12];
    const float* fin_w  = (const float*)d_in[13];
    const float* fin_b  = (const float*)d_in[14];
    const float* fn_g   = (const float*)d_in[15];
    const float* fn_b   = (const float*)d_in[16];
    const float* dec_w  = (const float*)d_in[17];
    const float* dec_b  = (const float*)d_in[18];

    float* out = (float*)d_out;
    float* states_full = out + (size_t)S_LEN * BB * VOC;  // [S+1][B][NHID]

    init_kernel<<<BB, 256>>>(h0, kc, vc, states_full);
    embed_kernel<<<S_LEN * BB, 256>>>(obs, enc_w);
    split_emb_kernel<<<(S_LEN * BB * NHID) / 1024, 256>>>();
    split_qw<<<(NHID * 2 * NHID) / 1024, 256>>>(q_w);
    split_iw<<<(4 * NHID * 4 * NHID) / 1024, 256>>>(int_w);
    split_fw<<<(3 * NHID * 4 * NHID) / 1024, 256>>>(fin_w);
    split_decw<<<(VOC * NHID) / 1024, 256>>>(dec_w);

    cudaFuncSetAttribute(rnn_kernel, cudaFuncAttributeMaxDynamicSharedMemorySize, 2 * RBUF);
    rnn_kernel<<<NCTA, TPB, 2 * RBUF>>>(q_b, qn_g, qn_b, int_b, intn_g, intn_b,
                                        fin_b, fn_g, fn_b, states_full);

    split_states<<<(S_LEN * BB * NHID) / 1024, 256>>>(states_full + (size_t)BB * NHID);
    cudaFuncSetAttribute(dec_mma_kernel, cudaFuncAttributeMaxDynamicSharedMemorySize, 2 * BUF_BYTES);
    dec_mma_kernel<<<dim3((S_LEN * BB) / DM, VOC / DN), 256, 2 * BUF_BYTES>>>(dec_b, out);
}